// round 7
// baseline (speedup 1.0000x reference)
#include <cuda_runtime.h>
#include <stdint.h>

#define N_ROWS 16384
#define K_DIM  200
#define H_DIM  768
#define NB_AUG 10
#define NELTS  (16384u * 200u)

// ---------------- scratch (static device globals; no allocations) ----------
__device__ float g_x [(size_t)N_ROWS * K_DIM];   // fc output [N][K]
__device__ float g_xT[(size_t)K_DIM * N_ROWS];   // transposed [K][N]
__device__ float g_mu[K_DIM];
__device__ float g_sd[K_DIM];                    // sqrt(var + 1e-5)
__device__ float g_rx[NELTS];                    // first-iter normal  x1
__device__ float g_ru[NELTS];                    // first-iter uniform U1

// ---------------- threefry2x32 (JAX-exact) ---------------------------------
__device__ __forceinline__ uint2 tf2x32(uint32_t k0, uint32_t k1,
                                        uint32_t x0, uint32_t x1) {
    uint32_t ks2 = k0 ^ k1 ^ 0x1BD11BDAu;
    x0 += k0; x1 += k1;
#define TFR(r) { x0 += x1; x1 = __funnelshift_l(x1, x1, (r)); x1 ^= x0; }
    TFR(13) TFR(15) TFR(26) TFR(6)
    x0 += k1;  x1 += ks2 + 1u;
    TFR(17) TFR(29) TFR(16) TFR(24)
    x0 += ks2; x1 += k0 + 2u;
    TFR(13) TFR(15) TFR(26) TFR(6)
    x0 += k0;  x1 += k1 + 3u;
    TFR(17) TFR(29) TFR(16) TFR(24)
    x0 += k1;  x1 += ks2 + 4u;
    TFR(13) TFR(15) TFR(26) TFR(6)
    x0 += ks2; x1 += k0 + 5u;
#undef TFR
    return make_uint2(x0, x1);
}

__device__ __forceinline__ float bits_to_f01(uint32_t bits) {
    return __fsub_rn(__uint_as_float((bits >> 9) | 0x3f800000u), 1.0f);
}

// ---------------- XLA/Giles erfinv (f32), no FMA contraction ---------------
__device__ __forceinline__ float erfinv_xla(float x) {
    float w = -log1pf(-__fmul_rn(x, x));
    float p;
    if (w < 5.0f) {
        w = __fsub_rn(w, 2.5f);
        p = 2.81022636e-08f;
        p = __fadd_rn( 3.43273939e-07f, __fmul_rn(p, w));
        p = __fadd_rn(-3.5233877e-06f,  __fmul_rn(p, w));
        p = __fadd_rn(-4.39150654e-06f, __fmul_rn(p, w));
        p = __fadd_rn( 0.00021858087f,  __fmul_rn(p, w));
        p = __fadd_rn(-0.00125372503f,  __fmul_rn(p, w));
        p = __fadd_rn(-0.00417768164f,  __fmul_rn(p, w));
        p = __fadd_rn( 0.246640727f,    __fmul_rn(p, w));
        p = __fadd_rn( 1.50140941f,     __fmul_rn(p, w));
    } else {
        w = __fsub_rn(sqrtf(w), 3.0f);
        p = -0.000200214257f;
        p = __fadd_rn( 0.000100950558f, __fmul_rn(p, w));
        p = __fadd_rn( 0.00134934322f,  __fmul_rn(p, w));
        p = __fadd_rn(-0.00367342844f,  __fmul_rn(p, w));
        p = __fadd_rn( 0.00573950773f,  __fmul_rn(p, w));
        p = __fadd_rn(-0.0076224613f,   __fmul_rn(p, w));
        p = __fadd_rn( 0.00943887047f,  __fmul_rn(p, w));
        p = __fadd_rn( 1.00167406f,     __fmul_rn(p, w));
        p = __fadd_rn( 2.83297682f,     __fmul_rn(p, w));
    }
    return __fmul_rn(p, x);
}

__device__ __forceinline__ float jax_normal_from_key(uint2 k) {
    uint2 nb = tf2x32(k.x, k.y, 0u, 0u);
    float f = bits_to_f01(nb.x ^ nb.y);
    float u = fmaxf(-0.99999994f, __fadd_rn(__fmul_rn(f, 2.0f), -0.99999994f));
    return __fmul_rn(__uint_as_float(0x3FB504F3u), erfinv_xla(u));
}

// ---------------- JAX gamma sampler (full fallback; Marsaglia-Tsang) -------
__device__ float jax_gamma(float aB, uint32_t i) {
    uint2 Ki  = tf2x32(0u, 42u, 0u, i);
    uint2 key = tf2x32(Ki.x, Ki.y, 0u, 0u);

    float d = __fsub_rn(aB, 0.33333334f);
    float c = __fdiv_rn(0.33333334f, sqrtf(d));
    float V = 1.0f;

    for (;;) {
        uint2 xkey = tf2x32(key.x, key.y, 0u, 1u);
        uint2 Ukey = tf2x32(key.x, key.y, 0u, 2u);
        float x, v;
        uint2 ik = xkey;
        for (;;) {
            uint2 sub = tf2x32(ik.x, ik.y, 0u, 1u);
            x = jax_normal_from_key(sub);
            v = __fadd_rn(1.0f, __fmul_rn(x, c));
            if (v > 0.0f) break;
            ik = tf2x32(ik.x, ik.y, 0u, 0u);
        }
        float X = __fmul_rn(x, x);
        V = __fmul_rn(__fmul_rn(v, v), v);
        uint2 ub = tf2x32(Ukey.x, Ukey.y, 0u, 0u);
        float U = bits_to_f01(ub.x ^ ub.y);

        float sq = __fsub_rn(1.0f, __fmul_rn(0.0331f, __fmul_rn(X, X)));
        if (U < sq) break;
        float rhs = __fadd_rn(__fmul_rn(X, 0.5f),
                    __fadd_rn(__fsub_rn(d, __fmul_rn(d, V)), __fmul_rn(d, logf(V))));
        if (logf(U) < rhs) break;
        key = tf2x32(key.x, key.y, 0u, 0u);
    }
    float z = __fmul_rn(d, V);
    return (z == 0.0f) ? 1.17549435e-38f : z;
}

// ---------------- fused: zero-waste GEMM-T + RNG precompute ----------------
// Block role by index: per group of 27 blocks, 5 do GEMM, 22 do RNG.
// GEMM-T: g_xT[k][n] = sum_h W[k][h]*hidden[n][h] + b[k].
//   Tile 40(k) x 128(n), BK=16, double-buffered. 8 warps as 2(k) x 4(n);
//   lanes 4(k) x 8(n); microtile 5x4. Exact 5x128 grid: ZERO padding waste.
//   FMA chain per out: ascending h, single acc, bias last => bitwise == g_x.
// RNG: per element i, the exact alpha-independent first-iteration chain:
//   Ki=TF((0,42),(0,i)); key=TF(Ki,(0,0)); xkey=TF(key,(0,1));
//   Ukey=TF(key,(0,2)); sub=TF(xkey,(0,1)); x1=normal(sub); U1=unif(Ukey).
#define GRID_GROUPS 128
#define FUSED_BLOCKS (GRID_GROUPS * 27)   // 3456: 640 gemm + 2816 rng

__global__ void __launch_bounds__(256, 2)
fused_gemm_rng(const float* __restrict__ A, const float* __restrict__ Wm,
               const float* __restrict__ bias) {
    __shared__ float Ws[2][16 * 41];    // [kk][40] rows padded to 41
    __shared__ float Hs[2][16 * 128];   // [kk][128] with chunk swizzle

    const int bx  = blockIdx.x;
    const int grp = bx / 27;
    const int r   = bx % 27;
    const int tid = threadIdx.x;

    if (r >= 5) {
        // ---------------- RNG block ----------------
        const uint32_t rid    = (uint32_t)grp * 22u + (uint32_t)(r - 5);
        const uint32_t stride = (uint32_t)GRID_GROUPS * 22u * 256u;  // 720896
        for (uint32_t i = rid * 256u + (uint32_t)tid; i < NELTS; i += stride) {
            uint2 Ki   = tf2x32(0u, 42u, 0u, i);
            uint2 key  = tf2x32(Ki.x, Ki.y, 0u, 0u);
            uint2 xkey = tf2x32(key.x, key.y, 0u, 1u);
            uint2 Ukey = tf2x32(key.x, key.y, 0u, 2u);
            uint2 sub  = tf2x32(xkey.x, xkey.y, 0u, 1u);
            float x1   = jax_normal_from_key(sub);
            uint2 ub   = tf2x32(Ukey.x, Ukey.y, 0u, 0u);
            float U1   = bits_to_f01(ub.x ^ ub.y);
            g_rx[i] = x1;
            g_ru[i] = U1;
        }
        return;
    }

    // ---------------- GEMM block ----------------
    const int g  = grp * 5 + r;          // 0..639
    const int k0 = (g % 5) * 40;
    const int n0 = (g / 5) * 128;

    const int w   = tid >> 5;
    const int l   = tid & 31;
    const int wk  = w & 1;       // 0..1  (k-warps)
    const int wn2 = w >> 1;      // 0..3  (n-warps)
    const int lk  = l & 3;       // 0..3
    const int ln  = l >> 2;      // 0..7

    const int abase = wk * 20 + lk * 5;                 // k-frag rows (5)
    const int cB    = wn2 * 8 + ln;                     // 16B chunk index
    const int offB  = ((cB ^ (cB >> 3)) << 2);          // swizzled word

    // global-load mapping
    const int krW = tid >> 2, hcW = tid & 3;            // W: threads 0..159
    const int ra0 = (tid * 2) >> 2,     ca0 = (tid * 2) & 3;   // H: 2 f4/thr
    const int ra1 = (tid * 2 + 1) >> 2, ca1 = (tid * 2 + 1) & 3;

    float acc[5][4];
#pragma unroll
    for (int i = 0; i < 5; i++)
#pragma unroll
        for (int j = 0; j < 4; j++) acc[i][j] = 0.0f;

#define STS_W(Sb, v) do {                                   \
        (Sb)[(hcW * 4 + 0) * 41 + krW] = (v).x;             \
        (Sb)[(hcW * 4 + 1) * 41 + krW] = (v).y;             \
        (Sb)[(hcW * 4 + 2) * 41 + krW] = (v).z;             \
        (Sb)[(hcW * 4 + 3) * 41 + krW] = (v).w;             \
    } while (0)
#define STS_H(Sb, c4, rr, v) do {                           \
        int cc = (rr) >> 2;                                 \
        int w_ = ((cc ^ (cc >> 3)) << 2) + ((rr) & 3);      \
        (Sb)[((c4) * 4 + 0) * 128 + w_] = (v).x;            \
        (Sb)[((c4) * 4 + 1) * 128 + w_] = (v).y;            \
        (Sb)[((c4) * 4 + 2) * 128 + w_] = (v).z;            \
        (Sb)[((c4) * 4 + 3) * 128 + w_] = (v).w;            \
    } while (0)

    // ---- tile 0 ----
    {
        if (tid < 160) {
            float4 wv = *reinterpret_cast<const float4*>(
                &Wm[(size_t)(k0 + krW) * H_DIM + hcW * 4]);
            STS_W(Ws[0], wv);
        }
        float4 h0v = *reinterpret_cast<const float4*>(&A[(size_t)(n0 + ra0) * H_DIM + ca0 * 4]);
        float4 h1v = *reinterpret_cast<const float4*>(&A[(size_t)(n0 + ra1) * H_DIM + ca1 * 4]);
        STS_H(Hs[0], ca0, ra0, h0v);
        STS_H(Hs[0], ca1, ra1, h1v);
    }
    __syncthreads();

    int buf = 0;
    for (int t = 1; t <= H_DIM / 16; t++) {
        float4 wv, h0v, h1v;
        const bool more = (t < H_DIM / 16);
        if (more) {
            const int h0 = t * 16;
            if (tid < 160)
                wv = *reinterpret_cast<const float4*>(
                    &Wm[(size_t)(k0 + krW) * H_DIM + h0 + hcW * 4]);
            h0v = *reinterpret_cast<const float4*>(&A[(size_t)(n0 + ra0) * H_DIM + h0 + ca0 * 4]);
            h1v = *reinterpret_cast<const float4*>(&A[(size_t)(n0 + ra1) * H_DIM + h0 + ca1 * 4]);
        }
#pragma unroll
        for (int kk = 0; kk < 16; kk++) {
            const float* Wb = &Ws[buf][kk * 41];
            const float* Hb = &Hs[buf][kk * 128];
            float av[5];
#pragma unroll
            for (int j = 0; j < 5; j++) av[j] = Wb[abase + j];
            float4 fb = *reinterpret_cast<const float4*>(Hb + offB);
            float bv[4] = {fb.x, fb.y, fb.z, fb.w};
#pragma unroll
            for (int i = 0; i < 5; i++)
#pragma unroll
                for (int j = 0; j < 4; j++)
                    acc[i][j] = fmaf(av[i], bv[j], acc[i][j]);
        }
        if (more) {
            int nb = buf ^ 1;
            if (tid < 160) STS_W(Ws[nb], wv);
            STS_H(Hs[nb], ca0, ra0, h0v);
            STS_H(Hs[nb], ca1, ra1, h1v);
            __syncthreads();
            buf = nb;
        }
    }
#undef STS_W
#undef STS_H

    const int ncol = n0 + wn2 * 32 + ln * 4;
#pragma unroll
    for (int i = 0; i < 5; i++) {
        const int krow = k0 + abase + i;      // always < 200
        const float bb = bias[krow];
        float4 o = make_float4(acc[i][0] + bb, acc[i][1] + bb,
                               acc[i][2] + bb, acc[i][3] + bb);
        *reinterpret_cast<float4*>(&g_xT[(size_t)krow * N_ROWS + ncol]) = o;
    }
}

// ---------------- transpose g_xT [K][N] -> g_x [N][K] ----------------------
__global__ void __launch_bounds__(256) transpose_kernel() {
    __shared__ float tile[32][33];
    const int k0 = blockIdx.x * 32;
    const int n0 = blockIdx.y * 32;
    const int tx = threadIdx.x & 31;
    const int ty = threadIdx.x >> 5;      // 0..7
#pragma unroll
    for (int q = 0; q < 4; q++) {
        int k = k0 + ty + q * 8;
        float v = 0.0f;
        if (k < K_DIM) v = g_xT[(size_t)k * N_ROWS + n0 + tx];
        tile[ty + q * 8][tx] = v;
    }
    __syncthreads();
#pragma unroll
    for (int q = 0; q < 4; q++) {
        int n = n0 + ty + q * 8;
        int k = k0 + tx;
        if (k < K_DIM) g_x[(size_t)n * K_DIM + k] = tile[tx][ty + q * 8];
    }
}

// ---------------- per-column mean / std (reads g_xT, coalesced) ------------
// EXACT partial order (n = t + 256j ascending) and tree as the passing
// versions => bitwise-identical mu/sd.
__global__ void __launch_bounds__(256) colstats_kernel() {
    const int k = blockIdx.x;
    const int t = threadIdx.x;
    const float* __restrict__ row = &g_xT[(size_t)k * N_ROWS];
    __shared__ float sm[256];

    float s = 0.0f;
    for (int j = 0; j < 64; j++) s += row[j * 256 + t];
    sm[t] = s; __syncthreads();
    for (int st = 128; st > 0; st >>= 1) {
        if (t < st) sm[t] += sm[t + st];
        __syncthreads();
    }
    float mu = sm[0] / 16384.0f;
    __syncthreads();

    float v = 0.0f;
    for (int j = 0; j < 64; j++) {
        float dd = row[j * 256 + t] - mu;
        v += dd * dd;
    }
    sm[t] = v; __syncthreads();
    for (int st = 128; st > 0; st >>= 1) {
        if (t < st) sm[t] += sm[t + st];
        __syncthreads();
    }
    if (t == 0) {
        g_mu[k] = mu;
        g_sd[k] = sqrtf(sm[0] / 16384.0f + 1e-5f);
    }
}

// ---------------- finish: softplus -> gamma(fast path) -> u-prod -> norm ---
__global__ void __launch_bounds__(224)
finish_kernel(const float* __restrict__ u, float* __restrict__ out) {
    int n = blockIdx.x;
    int k = threadIdx.x;
    float g = 0.0f;

    if (k < K_DIM) {
        float xv = g_x[(size_t)n * K_DIM + k];
        float xn = __fdiv_rn(__fsub_rn(xv, g_mu[k]), g_sd[k]);
        float sp = __fadd_rn(fmaxf(xn, 0.0f), log1pf(expf(-fabsf(xn))));
        float alphas = fmaxf(1e-5f, sp);
        float aB = __fadd_rn(alphas, 10.0f);

        uint32_t flat = (uint32_t)n * K_DIM + (uint32_t)k;

        // ---- fast path from precomputed first-iteration (x1, U1) ----
        float d = __fsub_rn(aB, 0.33333334f);
        float c = __fdiv_rn(0.33333334f, sqrtf(d));
        float x1 = g_rx[flat];
        float U1 = g_ru[flat];
        float v  = __fadd_rn(1.0f, __fmul_rn(x1, c));
        float gam;
        bool done = false;
        if (v > 0.0f) {
            float X = __fmul_rn(x1, x1);
            float V = __fmul_rn(__fmul_rn(v, v), v);
            float sq = __fsub_rn(1.0f, __fmul_rn(0.0331f, __fmul_rn(X, X)));
            bool acc = (U1 < sq);
            if (!acc) {
                float rhs = __fadd_rn(__fmul_rn(X, 0.5f),
                            __fadd_rn(__fsub_rn(d, __fmul_rn(d, V)),
                                      __fmul_rn(d, logf(V))));
                acc = (logf(U1) < rhs);
            }
            if (acc) {
                float z = __fmul_rn(d, V);
                gam = (z == 0.0f) ? 1.17549435e-38f : z;
                done = true;
            }
        }
        if (!done) gam = jax_gamma(aB, flat);   // rare slow path, bit-exact

        float prod = 1.0f;
#pragma unroll
        for (int rr = 0; rr < NB_AUG; rr++) {
            float uu = u[(size_t)rr * N_ROWS * K_DIM + (size_t)n * K_DIM + k];
            float av = __fadd_rn(alphas, (float)rr);
            float up = __fadd_rn(__powf(uu, __fdividef(1.0f, av)), 1e-10f);
            prod = __fmul_rn(prod, up);
        }
        g = __fmul_rn(prod, gam);
    }

    __shared__ float sm[256];
    sm[threadIdx.x] = g;
    if (threadIdx.x < 32) sm[224 + threadIdx.x] = 0.0f;
    __syncthreads();
    for (int st = 128; st > 0; st >>= 1) {
        if (threadIdx.x < st) sm[threadIdx.x] += sm[threadIdx.x + st];
        __syncthreads();
    }
    float rowsum = sm[0];

    if (k < K_DIM)
        out[(size_t)n * K_DIM + k] = __fdiv_rn(g, rowsum);
}

// ---------------- launcher --------------------------------------------------
extern "C" void kernel_launch(void* const* d_in, const int* in_sizes, int n_in,
                              void* d_out, int out_size) {
    const float* hidden = (const float*)d_in[0];   // [16384, 768]
    const float* W      = (const float*)d_in[1];   // [200, 768]
    const float* bias   = (const float*)d_in[2];   // [200]
    const float* u      = (const float*)d_in[3];   // [10, 16384, 200]
    float* out = (float*)d_out;                    // [16384, 200]

    fused_gemm_rng<<<FUSED_BLOCKS, 256>>>(hidden, W, bias);
    transpose_kernel<<<dim3(7, 512), 256>>>();
    colstats_kernel<<<K_DIM, 256>>>();
    finish_kernel<<<N_ROWS, 224>>>(u, out);
}

// round 9
// speedup vs baseline: 1.1277x; 1.1277x over previous
#include <cuda_runtime.h>
#include <stdint.h>

#define N_ROWS 16384
#define K_DIM  200
#define H_DIM  768
#define NB_AUG 10
#define NELTS  (16384u * 200u)

// ---------------- scratch (static device globals; no allocations) ----------
__device__ float g_x [(size_t)N_ROWS * K_DIM];   // fc output [N][K]
__device__ float g_xT[(size_t)K_DIM * N_ROWS];   // transposed [K][N]
__device__ float g_mu[K_DIM];
__device__ float g_sd[K_DIM];                    // sqrt(var + 1e-5)
__device__ float g_rx[NELTS];                    // first-iter normal  x1
__device__ float g_ru[NELTS];                    // first-iter uniform U1

// ---------------- threefry2x32 (JAX-exact) ---------------------------------
__device__ __forceinline__ uint2 tf2x32(uint32_t k0, uint32_t k1,
                                        uint32_t x0, uint32_t x1) {
    uint32_t ks2 = k0 ^ k1 ^ 0x1BD11BDAu;
    x0 += k0; x1 += k1;
#define TFR(r) { x0 += x1; x1 = __funnelshift_l(x1, x1, (r)); x1 ^= x0; }
    TFR(13) TFR(15) TFR(26) TFR(6)
    x0 += k1;  x1 += ks2 + 1u;
    TFR(17) TFR(29) TFR(16) TFR(24)
    x0 += ks2; x1 += k0 + 2u;
    TFR(13) TFR(15) TFR(26) TFR(6)
    x0 += k0;  x1 += k1 + 3u;
    TFR(17) TFR(29) TFR(16) TFR(24)
    x0 += k1;  x1 += ks2 + 4u;
    TFR(13) TFR(15) TFR(26) TFR(6)
    x0 += ks2; x1 += k0 + 5u;
#undef TFR
    return make_uint2(x0, x1);
}

__device__ __forceinline__ float bits_to_f01(uint32_t bits) {
    return __fsub_rn(__uint_as_float((bits >> 9) | 0x3f800000u), 1.0f);
}

// ---------------- XLA/Giles erfinv (f32), no FMA contraction ---------------
__device__ __forceinline__ float erfinv_xla(float x) {
    float w = -log1pf(-__fmul_rn(x, x));
    float p;
    if (w < 5.0f) {
        w = __fsub_rn(w, 2.5f);
        p = 2.81022636e-08f;
        p = __fadd_rn( 3.43273939e-07f, __fmul_rn(p, w));
        p = __fadd_rn(-3.5233877e-06f,  __fmul_rn(p, w));
        p = __fadd_rn(-4.39150654e-06f, __fmul_rn(p, w));
        p = __fadd_rn( 0.00021858087f,  __fmul_rn(p, w));
        p = __fadd_rn(-0.00125372503f,  __fmul_rn(p, w));
        p = __fadd_rn(-0.00417768164f,  __fmul_rn(p, w));
        p = __fadd_rn( 0.246640727f,    __fmul_rn(p, w));
        p = __fadd_rn( 1.50140941f,     __fmul_rn(p, w));
    } else {
        w = __fsub_rn(sqrtf(w), 3.0f);
        p = -0.000200214257f;
        p = __fadd_rn( 0.000100950558f, __fmul_rn(p, w));
        p = __fadd_rn( 0.00134934322f,  __fmul_rn(p, w));
        p = __fadd_rn(-0.00367342844f,  __fmul_rn(p, w));
        p = __fadd_rn( 0.00573950773f,  __fmul_rn(p, w));
        p = __fadd_rn(-0.0076224613f,   __fmul_rn(p, w));
        p = __fadd_rn( 0.00943887047f,  __fmul_rn(p, w));
        p = __fadd_rn( 1.00167406f,     __fmul_rn(p, w));
        p = __fadd_rn( 2.83297682f,     __fmul_rn(p, w));
    }
    return __fmul_rn(p, x);
}

__device__ __forceinline__ float jax_normal_from_key(uint2 k) {
    uint2 nb = tf2x32(k.x, k.y, 0u, 0u);
    float f = bits_to_f01(nb.x ^ nb.y);
    float u = fmaxf(-0.99999994f, __fadd_rn(__fmul_rn(f, 2.0f), -0.99999994f));
    return __fmul_rn(__uint_as_float(0x3FB504F3u), erfinv_xla(u));
}

// ---------------- JAX gamma sampler (full fallback; Marsaglia-Tsang) -------
__device__ float jax_gamma(float aB, uint32_t i) {
    uint2 Ki  = tf2x32(0u, 42u, 0u, i);
    uint2 key = tf2x32(Ki.x, Ki.y, 0u, 0u);

    float d = __fsub_rn(aB, 0.33333334f);
    float c = __fdiv_rn(0.33333334f, sqrtf(d));
    float V = 1.0f;

    for (;;) {
        uint2 xkey = tf2x32(key.x, key.y, 0u, 1u);
        uint2 Ukey = tf2x32(key.x, key.y, 0u, 2u);
        float x, v;
        uint2 ik = xkey;
        for (;;) {
            uint2 sub = tf2x32(ik.x, ik.y, 0u, 1u);
            x = jax_normal_from_key(sub);
            v = __fadd_rn(1.0f, __fmul_rn(x, c));
            if (v > 0.0f) break;
            ik = tf2x32(ik.x, ik.y, 0u, 0u);
        }
        float X = __fmul_rn(x, x);
        V = __fmul_rn(__fmul_rn(v, v), v);
        uint2 ub = tf2x32(Ukey.x, Ukey.y, 0u, 0u);
        float U = bits_to_f01(ub.x ^ ub.y);

        float sq = __fsub_rn(1.0f, __fmul_rn(0.0331f, __fmul_rn(X, X)));
        if (U < sq) break;
        float rhs = __fadd_rn(__fmul_rn(X, 0.5f),
                    __fadd_rn(__fsub_rn(d, __fmul_rn(d, V)), __fmul_rn(d, logf(V))));
        if (logf(U) < rhs) break;
        key = tf2x32(key.x, key.y, 0u, 0u);
    }
    float z = __fmul_rn(d, V);
    return (z == 0.0f) ? 1.17549435e-38f : z;
}

// ---------------- fused: zero-waste GEMM-T + RNG precompute ----------------
// Role assignment: classic launch places bids b and b+148 on the SAME SM.
// We alternate roles per 148-chunk, so every SM holds 1 GEMM + 1 RNG block:
//   chunk c = bx/148:  c even (c<8) -> GEMM, c odd -> RNG;
//   chunk 8 (96 blocks): first 48 GEMM, last 48 RNG.
// 640 GEMM blocks (tile 40k x 128n, zero padding) + 640 RNG blocks.
// GEMM saturates the FMA pipe (rt=2); threefry RNG runs on the ALU pipe
// (rt=2) using the complementary issue slots -> near-free overlap.
#define FUSED_BLOCKS 1280
#define RNG_STRIDE   (640u * 256u)

__global__ void __launch_bounds__(256, 2)
fused_gemm_rng(const float* __restrict__ A, const float* __restrict__ Wm,
               const float* __restrict__ bias) {
    __shared__ float Ws[2][16 * 41];    // [kk][40] rows padded to 41
    __shared__ float Hs[2][16 * 128];   // [kk][128] with chunk swizzle

    const int bx  = blockIdx.x;
    const int c   = bx / 148;
    const int o   = bx % 148;
    const int tid = threadIdx.x;

    bool is_gemm;
    int  idx;
    if (c < 8) {
        is_gemm = (c & 1) == 0;
        idx = (c >> 1) * 148 + o;
    } else {                 // c == 8, o in 0..95
        is_gemm = (o < 48);
        idx = 592 + (is_gemm ? o : (o - 48));
    }

    if (!is_gemm) {
        // ---------------- RNG block (idx 0..639) ----------------
        for (uint32_t i = (uint32_t)idx * 256u + (uint32_t)tid; i < NELTS;
             i += RNG_STRIDE) {
            uint2 Ki   = tf2x32(0u, 42u, 0u, i);
            uint2 key  = tf2x32(Ki.x, Ki.y, 0u, 0u);
            uint2 xkey = tf2x32(key.x, key.y, 0u, 1u);
            uint2 Ukey = tf2x32(key.x, key.y, 0u, 2u);
            uint2 sub  = tf2x32(xkey.x, xkey.y, 0u, 1u);
            float x1   = jax_normal_from_key(sub);
            uint2 ub   = tf2x32(Ukey.x, Ukey.y, 0u, 0u);
            float U1   = bits_to_f01(ub.x ^ ub.y);
            g_rx[i] = x1;
            g_ru[i] = U1;
        }
        return;
    }

    // ---------------- GEMM block (idx 0..639) ----------------
    const int k0 = (idx % 5) * 40;
    const int n0 = (idx / 5) * 128;

    const int w   = tid >> 5;
    const int l   = tid & 31;
    const int wk  = w & 1;       // 0..1  (k-warps)
    const int wn2 = w >> 1;      // 0..3  (n-warps)
    const int lk  = l & 3;       // 0..3
    const int ln  = l >> 2;      // 0..7

    const int abase = wk * 20 + lk * 5;                 // k-frag rows (5)
    const int cB    = wn2 * 8 + ln;                     // 16B chunk index
    const int offB  = ((cB ^ (cB >> 3)) << 2);          // swizzled word

    // global-load mapping
    const int krW = tid >> 2, hcW = tid & 3;            // W: threads 0..159
    const int ra0 = (tid * 2) >> 2,     ca0 = (tid * 2) & 3;   // H: 2 f4/thr
    const int ra1 = (tid * 2 + 1) >> 2, ca1 = (tid * 2 + 1) & 3;

    float acc[5][4];
#pragma unroll
    for (int i = 0; i < 5; i++)
#pragma unroll
        for (int j = 0; j < 4; j++) acc[i][j] = 0.0f;

#define STS_W(Sb, v) do {                                   \
        (Sb)[(hcW * 4 + 0) * 41 + krW] = (v).x;             \
        (Sb)[(hcW * 4 + 1) * 41 + krW] = (v).y;             \
        (Sb)[(hcW * 4 + 2) * 41 + krW] = (v).z;             \
        (Sb)[(hcW * 4 + 3) * 41 + krW] = (v).w;             \
    } while (0)
#define STS_H(Sb, c4, rr, v) do {                           \
        int cc = (rr) >> 2;                                 \
        int w_ = ((cc ^ (cc >> 3)) << 2) + ((rr) & 3);      \
        (Sb)[((c4) * 4 + 0) * 128 + w_] = (v).x;            \
        (Sb)[((c4) * 4 + 1) * 128 + w_] = (v).y;            \
        (Sb)[((c4) * 4 + 2) * 128 + w_] = (v).z;            \
        (Sb)[((c4) * 4 + 3) * 128 + w_] = (v).w;            \
    } while (0)

    // ---- tile 0 ----
    {
        if (tid < 160) {
            float4 wv = *reinterpret_cast<const float4*>(
                &Wm[(size_t)(k0 + krW) * H_DIM + hcW * 4]);
            STS_W(Ws[0], wv);
        }
        float4 h0v = *reinterpret_cast<const float4*>(&A[(size_t)(n0 + ra0) * H_DIM + ca0 * 4]);
        float4 h1v = *reinterpret_cast<const float4*>(&A[(size_t)(n0 + ra1) * H_DIM + ca1 * 4]);
        STS_H(Hs[0], ca0, ra0, h0v);
        STS_H(Hs[0], ca1, ra1, h1v);
    }
    __syncthreads();

    int buf = 0;
    for (int t = 1; t <= H_DIM / 16; t++) {
        float4 wv, h0v, h1v;
        const bool more = (t < H_DIM / 16);
        if (more) {
            const int h0 = t * 16;
            if (tid < 160)
                wv = *reinterpret_cast<const float4*>(
                    &Wm[(size_t)(k0 + krW) * H_DIM + h0 + hcW * 4]);
            h0v = *reinterpret_cast<const float4*>(&A[(size_t)(n0 + ra0) * H_DIM + h0 + ca0 * 4]);
            h1v = *reinterpret_cast<const float4*>(&A[(size_t)(n0 + ra1) * H_DIM + h0 + ca1 * 4]);
        }
#pragma unroll
        for (int kk = 0; kk < 16; kk++) {
            const float* Wb = &Ws[buf][kk * 41];
            const float* Hb = &Hs[buf][kk * 128];
            float av[5];
#pragma unroll
            for (int j = 0; j < 5; j++) av[j] = Wb[abase + j];
            float4 fb = *reinterpret_cast<const float4*>(Hb + offB);
            float bv[4] = {fb.x, fb.y, fb.z, fb.w};
#pragma unroll
            for (int i = 0; i < 5; i++)
#pragma unroll
                for (int j = 0; j < 4; j++)
                    acc[i][j] = fmaf(av[i], bv[j], acc[i][j]);
        }
        if (more) {
            int nb = buf ^ 1;
            if (tid < 160) STS_W(Ws[nb], wv);
            STS_H(Hs[nb], ca0, ra0, h0v);
            STS_H(Hs[nb], ca1, ra1, h1v);
            __syncthreads();
            buf = nb;
        }
    }
#undef STS_W
#undef STS_H

    const int ncol = n0 + wn2 * 32 + ln * 4;
#pragma unroll
    for (int i = 0; i < 5; i++) {
        const int krow = k0 + abase + i;      // always < 200
        const float bb = bias[krow];
        float4 ov = make_float4(acc[i][0] + bb, acc[i][1] + bb,
                                acc[i][2] + bb, acc[i][3] + bb);
        *reinterpret_cast<float4*>(&g_xT[(size_t)krow * N_ROWS + ncol]) = ov;
    }
}

// ---------------- transpose g_xT [K][N] -> g_x [N][K] ----------------------
__global__ void __launch_bounds__(256) transpose_kernel() {
    __shared__ float tile[32][33];
    const int k0 = blockIdx.x * 32;
    const int n0 = blockIdx.y * 32;
    const int tx = threadIdx.x & 31;
    const int ty = threadIdx.x >> 5;      // 0..7
#pragma unroll
    for (int q = 0; q < 4; q++) {
        int k = k0 + ty + q * 8;
        float v = 0.0f;
        if (k < K_DIM) v = g_xT[(size_t)k * N_ROWS + n0 + tx];
        tile[ty + q * 8][tx] = v;
    }
    __syncthreads();
#pragma unroll
    for (int q = 0; q < 4; q++) {
        int n = n0 + ty + q * 8;
        int k = k0 + tx;
        if (k < K_DIM) g_x[(size_t)n * K_DIM + k] = tile[tx][ty + q * 8];
    }
}

// ---------------- per-column mean / std (reads g_xT, coalesced) ------------
// EXACT partial order (n = t + 256j ascending) and tree as the passing
// versions => bitwise-identical mu/sd.
__global__ void __launch_bounds__(256) colstats_kernel() {
    const int k = blockIdx.x;
    const int t = threadIdx.x;
    const float* __restrict__ row = &g_xT[(size_t)k * N_ROWS];
    __shared__ float sm[256];

    float s = 0.0f;
    for (int j = 0; j < 64; j++) s += row[j * 256 + t];
    sm[t] = s; __syncthreads();
    for (int st = 128; st > 0; st >>= 1) {
        if (t < st) sm[t] += sm[t + st];
        __syncthreads();
    }
    float mu = sm[0] / 16384.0f;
    __syncthreads();

    float v = 0.0f;
    for (int j = 0; j < 64; j++) {
        float dd = row[j * 256 + t] - mu;
        v += dd * dd;
    }
    sm[t] = v; __syncthreads();
    for (int st = 128; st > 0; st >>= 1) {
        if (t < st) sm[t] += sm[t + st];
        __syncthreads();
    }
    if (t == 0) {
        g_mu[k] = mu;
        g_sd[k] = sqrtf(sm[0] / 16384.0f + 1e-5f);
    }
}

// ---------------- finish: softplus -> gamma(fast path) -> u-prod -> norm ---
__global__ void __launch_bounds__(224)
finish_kernel(const float* __restrict__ u, float* __restrict__ out) {
    int n = blockIdx.x;
    int k = threadIdx.x;
    float g = 0.0f;

    if (k < K_DIM) {
        float xv = g_x[(size_t)n * K_DIM + k];
        float xn = __fdiv_rn(__fsub_rn(xv, g_mu[k]), g_sd[k]);
        float sp = __fadd_rn(fmaxf(xn, 0.0f), log1pf(expf(-fabsf(xn))));
        float alphas = fmaxf(1e-5f, sp);
        float aB = __fadd_rn(alphas, 10.0f);

        uint32_t flat = (uint32_t)n * K_DIM + (uint32_t)k;

        // ---- fast path from precomputed first-iteration (x1, U1) ----
        float d = __fsub_rn(aB, 0.33333334f);
        float c = __fdiv_rn(0.33333334f, sqrtf(d));
        float x1 = g_rx[flat];
        float U1 = g_ru[flat];
        float v  = __fadd_rn(1.0f, __fmul_rn(x1, c));
        float gam;
        bool done = false;
        if (v > 0.0f) {
            float X = __fmul_rn(x1, x1);
            float V = __fmul_rn(__fmul_rn(v, v), v);
            float sq = __fsub_rn(1.0f, __fmul_rn(0.0331f, __fmul_rn(X, X)));
            bool acc = (U1 < sq);
            if (!acc) {
                float rhs = __fadd_rn(__fmul_rn(X, 0.5f),
                            __fadd_rn(__fsub_rn(d, __fmul_rn(d, V)),
                                      __fmul_rn(d, logf(V))));
                acc = (logf(U1) < rhs);
            }
            if (acc) {
                float z = __fmul_rn(d, V);
                gam = (z == 0.0f) ? 1.17549435e-38f : z;
                done = true;
            }
        }
        if (!done) gam = jax_gamma(aB, flat);   // rare slow path, bit-exact

        float prod = 1.0f;
#pragma unroll
        for (int rr = 0; rr < NB_AUG; rr++) {
            float uu = u[(size_t)rr * N_ROWS * K_DIM + (size_t)n * K_DIM + k];
            float av = __fadd_rn(alphas, (float)rr);
            float up = __fadd_rn(__powf(uu, __fdividef(1.0f, av)), 1e-10f);
            prod = __fmul_rn(prod, up);
        }
        g = __fmul_rn(prod, gam);
    }

    __shared__ float sm[256];
    sm[threadIdx.x] = g;
    if (threadIdx.x < 32) sm[224 + threadIdx.x] = 0.0f;
    __syncthreads();
    for (int st = 128; st > 0; st >>= 1) {
        if (threadIdx.x < st) sm[threadIdx.x] += sm[threadIdx.x + st];
        __syncthreads();
    }
    float rowsum = sm[0];

    if (k < K_DIM)
        out[(size_t)n * K_DIM + k] = __fdiv_rn(g, rowsum);
}

// ---------------- launcher --------------------------------------------------
extern "C" void kernel_launch(void* const* d_in, const int* in_sizes, int n_in,
                              void* d_out, int out_size) {
    const float* hidden = (const float*)d_in[0];   // [16384, 768]
    const float* W      = (const float*)d_in[1];   // [200, 768]
    const float* bias   = (const float*)d_in[2];   // [200]
    const float* u      = (const float*)d_in[3];   // [10, 16384, 200]
    float* out = (float*)d_out;                    // [16384, 200]

    fused_gemm_rng<<<FUSED_BLOCKS, 256>>>(hidden, W, bias);
    transpose_kernel<<<dim3(7, 512), 256>>>();
    colstats_kernel<<<K_DIM, 256>>>();
    finish_kernel<<<N_ROWS, 224>>>(u, out);
}